// round 8
// baseline (speedup 1.0000x reference)
#include <cuda_runtime.h>
#include <stdint.h>

#define Bq   4
#define Cq   16
#define Hq   512
#define Wq   512
#define HWq  (Hq * Wq)          // 262144
#define NODES (Bq * HWq)        // 1048576
#define NF_ELEMS (NODES * Cq)   // 16777216
#define SQ2f 1.41421356237f
#define ATTR_BLOCKS 512         // one per image row
#define TRANS_BLOCKS (NODES / 256)

// Fused kernel. Blocks [0,512): per-row 8-neighbor stencil -> edge_attr +
// float edge_index (2 cols/thread; horizontal halos come from neighbor lanes
// via shuffle, only warp-boundary lanes touch global for halo).
// Blocks [512,4608): BCHW -> (B*H*W, C) transpose.
__global__ void __launch_bounds__(256) fused_kernel(
    const float* __restrict__ grid, float* __restrict__ nf,
    float* __restrict__ ei_out, float* __restrict__ attr, int E)
{
    if (blockIdx.x >= ATTR_BLOCKS) {
        // ---------------- transpose part ----------------
        int node = (blockIdx.x - ATTR_BLOCKS) * 256 + threadIdx.x;
        int b  = node >> 18;
        int hw = node & (HWq - 1);
        const float* g = grid + (size_t)b * Cq * HWq + hw;

        float v[Cq];
#pragma unroll
        for (int c = 0; c < Cq; c++) v[c] = g[(size_t)c * HWq];

        float4* dst = (float4*)(nf + (size_t)node * Cq);
#pragma unroll
        for (int i = 0; i < 4; i++)
            dst[i] = make_float4(v[4*i], v[4*i+1], v[4*i+2], v[4*i+3]);
        return;
    }

    // ---------------- attr part ----------------
    const int h    = blockIdx.x;
    const int lane = threadIdx.x & 31;
    const int w0   = threadIdx.x * 2;
    const int w1   = w0 + 1;

    const int hu = (h > 0)      ? h - 1 : 0;
    const int hd = (h < Hq - 1) ? h + 1 : Hq - 1;

    const float* pc = grid + (size_t)h  * Wq;
    const float* pu = grid + (size_t)hu * Wq;
    const float* pd = grid + (size_t)hd * Wq;

    const int wm = (w0 > 0)      ? w0 - 1 : 0;   // clamped halo cols
    const int wp = (w1 < Wq - 1) ? w1 + 1 : Wq - 1;
    const bool edgeL = (lane == 0);
    const bool edgeR = (lane == 31);

    float a0[8], a1[8];
#pragma unroll
    for (int k = 0; k < 8; k++) { a0[k] = 0.0f; a1[k] = 0.0f; }

#pragma unroll 4
    for (int bc = 0; bc < Bq * Cq; bc++) {
        float2 cu = *(const float2*)(pc + w0);
        float2 uu = *(const float2*)(pu + w0);
        float2 dd = *(const float2*)(pd + w0);

        // halos from neighbor lanes
        float ul = __shfl_up_sync(0xffffffffu, uu.y, 1);
        float cl = __shfl_up_sync(0xffffffffu, cu.y, 1);
        float dl = __shfl_up_sync(0xffffffffu, dd.y, 1);
        float ur = __shfl_down_sync(0xffffffffu, uu.x, 1);
        float cr = __shfl_down_sync(0xffffffffu, cu.x, 1);
        float dr = __shfl_down_sync(0xffffffffu, dd.x, 1);
        if (edgeL) { ul = pu[wm]; cl = pc[wm]; dl = pd[wm]; }
        if (edgeR) { ur = pu[wp]; cr = pc[wp]; dr = pd[wp]; }

        a0[0] += fabsf(cu.x - ul);
        a0[1] += fabsf(cu.x - uu.x);
        a0[2] += fabsf(cu.x - uu.y);
        a0[3] += fabsf(cu.x - cl);
        a0[4] += fabsf(cu.x - cu.y);
        a0[5] += fabsf(cu.x - dl);
        a0[6] += fabsf(cu.x - dd.x);
        a0[7] += fabsf(cu.x - dd.y);

        a1[0] += fabsf(cu.y - uu.x);
        a1[1] += fabsf(cu.y - uu.y);
        a1[2] += fabsf(cu.y - ur);
        a1[3] += fabsf(cu.y - cu.x);
        a1[4] += fabsf(cu.y - cr);
        a1[5] += fabsf(cu.y - dd.x);
        a1[6] += fabsf(cu.y - dd.y);
        a1[7] += fabsf(cu.y - dr);

        pu += HWq; pc += HWq; pd += HWq;
    }

    // ---- analytic edge positions ----
    // edges per row: boundary rows 3+3+5*510 = 2556, interior 5+5+8*510 = 4090
    const int rowbase = (h == 0) ? 0 : (2556 + 4090 * (h - 1));
    const bool edgeRow = (h == 0) || (h == Hq - 1);
    const bool up_ok = (h > 0), dn_ok = (h < Hq - 1);

    const float dist[8] = {SQ2f, 1.0f, SQ2f, 1.0f, 1.0f, SQ2f, 1.0f, SQ2f};
    const int   doff[8] = {-Wq - 1, -Wq, -Wq + 1, -1, 1, Wq - 1, Wq, Wq + 1};
    const float inv = 1.0f / (float)(Bq * Cq);

#pragma unroll
    for (int j = 0; j < 2; j++) {
        const int w = w0 + j;
        const float* acc = (j == 0) ? a0 : a1;
        const bool l_ok = (w > 0), r_ok = (w < Wq - 1);

        const int within = (w == 0) ? 0 : (edgeRow ? (3 + 5 * (w - 1))
                                                   : (5 + 8 * (w - 1)));
        const int P = rowbase + within;
        const int n = h * Wq + w;

        const bool v[8] = { up_ok && l_ok, up_ok, up_ok && r_ok,
                            l_ok, r_ok,
                            dn_ok && l_ok, dn_ok, dn_ok && r_ok };

        int slot = 0;
#pragma unroll
        for (int k = 0; k < 8; k++) {
            if (v[k]) {
                int e = P + slot;
                ((float2*)attr)[e] = make_float2(dist[k], acc[k] * inv);
                ei_out[e]     = (float)n;
                ei_out[E + e] = (float)(n + doff[k]);
                slot++;
            }
        }
    }
}

extern "C" void kernel_launch(void* const* d_in, const int* in_sizes, int n_in,
                              void* d_out, int out_size)
{
    const float* grid = (const float*)d_in[0];
    const int E = in_sizes[1] / 2;

    float* out    = (float*)d_out;
    float* nf     = out;                    // [NODES, C]
    float* ei_out = out + NF_ELEMS;         // [2, E] as float
    float* attr   = ei_out + 2 * (size_t)E; // [E, 2]

    fused_kernel<<<ATTR_BLOCKS + TRANS_BLOCKS, 256>>>(grid, nf, ei_out, attr, E);
}

// round 9
// speedup vs baseline: 1.2359x; 1.2359x over previous
#include <cuda_runtime.h>
#include <stdint.h>

#define Bq   4
#define Cq   16
#define Hq   512
#define Wq   512
#define HWq  (Hq * Wq)          // 262144
#define NODES (Bq * HWq)        // 1048576
#define NF_ELEMS (NODES * Cq)   // 16777216
#define SQ2f 1.41421356237f
#define ATTR_BLOCKS 512         // one per image row
#define TRANS_BLOCKS (NODES / 256)

// Fused kernel.
// Blocks [0,512): per-row stencil. Each thread owns 2 columns and computes
// only the 4 FORWARD directions (right, down-left, down, down-right); each
// forward edge and its reverse are written together (identical dist/feature),
// with the reverse position computed analytically. Rows h-1 are never read.
// Blocks [512,4608): BCHW -> (B*H*W, C) transpose.
__global__ void __launch_bounds__(256) fused_kernel(
    const float* __restrict__ grid, float* __restrict__ nf,
    float* __restrict__ ei_out, float* __restrict__ attr, int E)
{
    if (blockIdx.x >= ATTR_BLOCKS) {
        // ---------------- transpose part ----------------
        int node = (blockIdx.x - ATTR_BLOCKS) * 256 + threadIdx.x;
        int b  = node >> 18;
        int hw = node & (HWq - 1);
        const float* g = grid + (size_t)b * Cq * HWq + hw;

        float v[Cq];
#pragma unroll
        for (int c = 0; c < Cq; c++) v[c] = g[(size_t)c * HWq];

        float4* dst = (float4*)(nf + (size_t)node * Cq);
#pragma unroll
        for (int i = 0; i < 4; i++)
            dst[i] = make_float4(v[4*i], v[4*i+1], v[4*i+2], v[4*i+3]);
        return;
    }

    // ---------------- attr part ----------------
    const int h  = blockIdx.x;
    const int w0 = threadIdx.x * 2;
    const int w1 = w0 + 1;

    const int hd = (h < Hq - 1) ? h + 1 : h;     // clamped (unused if bottom row)
    const float* pc = grid + (size_t)h  * Wq;
    const float* pd = grid + (size_t)hd * Wq;

    const int xr = (w0 + 2 < Wq) ? w0 + 2 : Wq - 1;  // clamped halo cols
    const int xl = (w0 > 0)      ? w0 - 1 : 0;

    // per-column accumulators: right, down-left, down, down-right
    float r0 = 0, l0 = 0, d0 = 0, g0 = 0;
    float r1 = 0, l1 = 0, d1 = 0, g1 = 0;

#pragma unroll 4
    for (int bc = 0; bc < Bq * Cq; bc++) {
        float2 c = *(const float2*)(pc + w0);
        float2 d = *(const float2*)(pd + w0);
        float cr  = pc[xr];
        float dll = pd[xl];
        float drr = pd[xr];

        r0 += fabsf(c.x - c.y);
        l0 += fabsf(c.x - dll);
        d0 += fabsf(c.x - d.x);
        g0 += fabsf(c.x - d.y);

        r1 += fabsf(c.y - cr);
        l1 += fabsf(c.y - d.x);
        d1 += fabsf(c.y - d.y);
        g1 += fabsf(c.y - drr);

        pc += HWq; pd += HWq;
    }

    // ---- analytic edge positions ----
    // edges per row: boundary rows 2556, interior 4090
    const int  rowbase  = (h == 0) ? 0 : (2556 + 4090 * (h - 1));
    const int  rowbase2 = 2556 + 4090 * h;           // rowbase(h+1), h+1 >= 1
    const bool edgeRow  = (h == 0) || (h == Hq - 1);
    const bool edgeRow2 = (h + 1 == Hq - 1);
    const bool up_ok = (h > 0), dn_ok = (h < Hq - 1);
    const float inv = 1.0f / (float)(Bq * Cq);

    float accs[2][4] = { {r0, l0, d0, g0}, {r1, l1, d1, g1} };

#pragma unroll
    for (int j = 0; j < 2; j++) {
        const int w = w0 + j;
        const int n = h * Wq + w;
        const bool l_ok = (w > 0), r_ok = (w < Wq - 1);

        const float fr = accs[j][0] * inv;
        const float fl = accs[j][1] * inv;
        const float fd = accs[j][2] * inv;
        const float fg = accs[j][3] * inv;

        const int Pn = rowbase + ((w == 0) ? 0 : (edgeRow ? (3 + 5 * (w - 1))
                                                          : (5 + 8 * (w - 1))));
        // forward slots at n (valid-offset prefix counts)
        const int upc   = up_ok ? (1 + (int)l_ok + (int)r_ok) : 0;
        const int slot4 = upc + (int)l_ok;
        const int slot5 = slot4 + (int)r_ok;
        const int slot6 = slot5 + (int)(dn_ok && l_ok);
        const int slot7 = slot6 + (int)dn_ok;

        if (r_ok) {  // k=4: right, and reverse (left of m=(h,w+1))
            int e = Pn + slot4;
            ((float2*)attr)[e] = make_float2(1.0f, fr);
            ei_out[e] = (float)n; ei_out[E + e] = (float)(n + 1);

            int wm = w + 1;
            int Pm = rowbase + (edgeRow ? (3 + 5 * (wm - 1)) : (5 + 8 * (wm - 1)));
            int sl = up_ok ? (2 + (int)(wm < Wq - 1)) : 0;
            int er = Pm + sl;
            ((float2*)attr)[er] = make_float2(1.0f, fr);
            ei_out[er] = (float)(n + 1); ei_out[E + er] = (float)n;
        }
        if (dn_ok) {
            if (l_ok) {  // k=5: down-left, reverse = up-right of m=(h+1,w-1)
                int e = Pn + slot5;
                ((float2*)attr)[e] = make_float2(SQ2f, fl);
                ei_out[e] = (float)n; ei_out[E + e] = (float)(n + Wq - 1);

                int wm = w - 1;
                int Pm = rowbase2 + ((wm == 0) ? 0 : (edgeRow2 ? (3 + 5 * (wm - 1))
                                                               : (5 + 8 * (wm - 1))));
                int er = Pm + 1 + (int)(wm > 0);
                ((float2*)attr)[er] = make_float2(SQ2f, fl);
                ei_out[er] = (float)(n + Wq - 1); ei_out[E + er] = (float)n;
            }
            {            // k=6: down, reverse = up of m=(h+1,w)
                int e = Pn + slot6;
                ((float2*)attr)[e] = make_float2(1.0f, fd);
                ei_out[e] = (float)n; ei_out[E + e] = (float)(n + Wq);

                int Pm = rowbase2 + ((w == 0) ? 0 : (edgeRow2 ? (3 + 5 * (w - 1))
                                                              : (5 + 8 * (w - 1))));
                int er = Pm + (int)l_ok;
                ((float2*)attr)[er] = make_float2(1.0f, fd);
                ei_out[er] = (float)(n + Wq); ei_out[E + er] = (float)n;
            }
            if (r_ok) {  // k=7: down-right, reverse = up-left of m=(h+1,w+1)
                int e = Pn + slot7;
                ((float2*)attr)[e] = make_float2(SQ2f, fg);
                ei_out[e] = (float)n; ei_out[E + e] = (float)(n + Wq + 1);

                int wm = w + 1;
                int Pm = rowbase2 + (edgeRow2 ? (3 + 5 * (wm - 1)) : (5 + 8 * (wm - 1)));
                int er = Pm;  // slot 0
                ((float2*)attr)[er] = make_float2(SQ2f, fg);
                ei_out[er] = (float)(n + Wq + 1); ei_out[E + er] = (float)n;
            }
        }
    }
}

extern "C" void kernel_launch(void* const* d_in, const int* in_sizes, int n_in,
                              void* d_out, int out_size)
{
    const float* grid = (const float*)d_in[0];
    const int E = in_sizes[1] / 2;

    float* out    = (float*)d_out;
    float* nf     = out;                    // [NODES, C]
    float* ei_out = out + NF_ELEMS;         // [2, E] as float
    float* attr   = ei_out + 2 * (size_t)E; // [E, 2]

    fused_kernel<<<ATTR_BLOCKS + TRANS_BLOCKS, 256>>>(grid, nf, ei_out, attr, E);
}

// round 11
// speedup vs baseline: 1.6407x; 1.3275x over previous
#include <cuda_runtime.h>
#include <stdint.h>

#define Bq   4
#define Cq   16
#define Hq   512
#define Wq   512
#define HWq  (Hq * Wq)          // 262144
#define NODES (Bq * HWq)        // 1048576
#define NF_ELEMS (NODES * Cq)   // 16777216
#define SQ2f 1.41421356237f
#define ATTR_BLOCKS 512
#define TRANS_BLOCKS (NODES / 256)     // 4096
#define EDGE_TOTAL   2091012
#define EW_BLOCKS    ((EDGE_TOTAL + 255) / 256)  // 8169
#define ROW0_EDGES   2556
#define ROWI_EDGES   4090
#define LASTROW_BASE (ROW0_EDGES + 510 * ROWI_EDGES)  // 2088456

// Fused kernel, three block roles:
//  [0, 512): forward-only stencil -> writes ONLY attr[2e+1] (feature diff)
//  [512, 4608): BCHW -> (B*H*W, C) transpose
//  [4608, 12777): edge-writer: e -> (src, dst, dist) analytically, coalesced
__global__ void __launch_bounds__(256) fused_kernel(
    const float* __restrict__ grid, float* __restrict__ nf,
    float* __restrict__ ei_out, float* __restrict__ attr, int E)
{
    if (blockIdx.x >= ATTR_BLOCKS + TRANS_BLOCKS) {
        // ---------------- edge-writer part ----------------
        int e = (blockIdx.x - ATTR_BLOCKS - TRANS_BLOCKS) * 256 + threadIdx.x;
        if (e >= E) return;

        int h, r;
        if (e < ROW0_EDGES)          { h = 0;   r = e; }
        else if (e >= LASTROW_BASE)  { h = 511; r = e - LASTROW_BASE; }
        else { int t = e - ROW0_EDGES; h = 1 + t / ROWI_EDGES; r = t % ROWI_EDGES; }

        const bool edgeRow = (h == 0) || (h == Hq - 1);
        int w, slot;
        if (edgeRow) {
            if (r < 3)              { w = 0;       slot = r; }
            else if (r >= 2553)     { w = Wq - 1;  slot = r - 2553; }
            else                    { w = 1 + (r - 3) / 5; slot = (r - 3) % 5; }
        } else {
            if (r < 5)              { w = 0;       slot = r; }
            else if (r >= 4085)     { w = Wq - 1;  slot = r - 4085; }
            else                    { w = 1 + (r - 5) / 8; slot = (r - 5) % 8; }
        }

        const bool up_ok = (h > 0), dn_ok = (h < Hq - 1);
        const bool l_ok = (w > 0),  r_ok  = (w < Wq - 1);
        const bool v[8] = { up_ok && l_ok, up_ok, up_ok && r_ok,
                            l_ok, r_ok,
                            dn_ok && l_ok, dn_ok, dn_ok && r_ok };
        const int   doff[8] = {-Wq - 1, -Wq, -Wq + 1, -1, 1, Wq - 1, Wq, Wq + 1};
        const float dtab[8] = {SQ2f, 1.0f, SQ2f, 1.0f, 1.0f, SQ2f, 1.0f, SQ2f};

        int k = 0, cnt = 0;
#pragma unroll
        for (int kk = 0; kk < 8; kk++) {
            if (v[kk]) { if (cnt == slot) k = kk; cnt++; }
        }

        int n = h * Wq + w;
        ei_out[e]     = (float)n;
        ei_out[E + e] = (float)(n + doff[k]);
        attr[2 * e]   = dtab[k];
        return;
    }

    if (blockIdx.x >= ATTR_BLOCKS) {
        // ---------------- transpose part ----------------
        int node = (blockIdx.x - ATTR_BLOCKS) * 256 + threadIdx.x;
        int b  = node >> 18;
        int hw = node & (HWq - 1);
        const float* g = grid + (size_t)b * Cq * HWq + hw;

        float v[Cq];
#pragma unroll
        for (int c = 0; c < Cq; c++) v[c] = g[(size_t)c * HWq];

        float4* dst = (float4*)(nf + (size_t)node * Cq);
#pragma unroll
        for (int i = 0; i < 4; i++)
            dst[i] = make_float4(v[4*i], v[4*i+1], v[4*i+2], v[4*i+3]);
        return;
    }

    // ---------------- attr (stencil) part ----------------
    const int h  = blockIdx.x;
    const int w0 = threadIdx.x * 2;

    const int hd = (h < Hq - 1) ? h + 1 : h;
    const float* pc = grid + (size_t)h  * Wq;
    const float* pd = grid + (size_t)hd * Wq;

    const int xr = (w0 + 2 < Wq) ? w0 + 2 : Wq - 1;
    const int xl = (w0 > 0)      ? w0 - 1 : 0;

    float r0 = 0, l0 = 0, d0 = 0, g0 = 0;
    float r1 = 0, l1 = 0, d1 = 0, g1 = 0;

#pragma unroll 4
    for (int bc = 0; bc < Bq * Cq; bc++) {
        float2 c = *(const float2*)(pc + w0);
        float2 d = *(const float2*)(pd + w0);
        float cr  = pc[xr];
        float dll = pd[xl];
        float drr = pd[xr];

        r0 += fabsf(c.x - c.y);
        l0 += fabsf(c.x - dll);
        d0 += fabsf(c.x - d.x);
        g0 += fabsf(c.x - d.y);

        r1 += fabsf(c.y - cr);
        l1 += fabsf(c.y - d.x);
        d1 += fabsf(c.y - d.y);
        g1 += fabsf(c.y - drr);

        pc += HWq; pd += HWq;
    }

    const int  rowbase  = (h == 0) ? 0 : (ROW0_EDGES + ROWI_EDGES * (h - 1));
    const int  rowbase2 = ROW0_EDGES + ROWI_EDGES * h;        // rowbase(h+1)
    const bool edgeRow  = (h == 0) || (h == Hq - 1);
    const bool edgeRow2 = (h + 1 == Hq - 1);
    const bool up_ok = (h > 0), dn_ok = (h < Hq - 1);
    const float inv = 1.0f / (float)(Bq * Cq);

    float accs[2][4] = { {r0, l0, d0, g0}, {r1, l1, d1, g1} };

#pragma unroll
    for (int j = 0; j < 2; j++) {
        const int w = w0 + j;
        const bool l_ok = (w > 0), r_ok = (w < Wq - 1);

        const float fr = accs[j][0] * inv;
        const float fl = accs[j][1] * inv;
        const float fd = accs[j][2] * inv;
        const float fg = accs[j][3] * inv;

        const int Pn = rowbase + ((w == 0) ? 0 : (edgeRow ? (3 + 5 * (w - 1))
                                                          : (5 + 8 * (w - 1))));
        const int upc   = up_ok ? (1 + (int)l_ok + (int)r_ok) : 0;
        const int slot4 = upc + (int)l_ok;
        const int slot5 = slot4 + (int)r_ok;
        const int slot6 = slot5 + (int)(dn_ok && l_ok);
        const int slot7 = slot6 + (int)dn_ok;

        if (r_ok) {  // right + its reverse (left of (h,w+1))
            attr[2 * (Pn + slot4) + 1] = fr;
            int wm = w + 1;
            int Pm = rowbase + (edgeRow ? (3 + 5 * (wm - 1)) : (5 + 8 * (wm - 1)));
            int sl = up_ok ? (2 + (int)(wm < Wq - 1)) : 0;
            attr[2 * (Pm + sl) + 1] = fr;
        }
        if (dn_ok) {
            if (l_ok) {  // down-left + reverse (up-right of (h+1,w-1))
                attr[2 * (Pn + slot5) + 1] = fl;
                int wm = w - 1;
                int Pm = rowbase2 + ((wm == 0) ? 0 : (edgeRow2 ? (3 + 5 * (wm - 1))
                                                               : (5 + 8 * (wm - 1))));
                attr[2 * (Pm + 1 + (int)(wm > 0)) + 1] = fl;
            }
            {            // down + reverse (up of (h+1,w))
                attr[2 * (Pn + slot6) + 1] = fd;
                int Pm = rowbase2 + ((w == 0) ? 0 : (edgeRow2 ? (3 + 5 * (w - 1))
                                                              : (5 + 8 * (w - 1))));
                attr[2 * (Pm + (int)l_ok) + 1] = fd;
            }
            if (r_ok) {  // down-right + reverse (up-left of (h+1,w+1))
                attr[2 * (Pn + slot7) + 1] = fg;
                int wm = w + 1;
                int Pm = rowbase2 + (edgeRow2 ? (3 + 5 * (wm - 1)) : (5 + 8 * (wm - 1)));
                attr[2 * Pm + 1] = fg;
            }
        }
    }
}

extern "C" void kernel_launch(void* const* d_in, const int* in_sizes, int n_in,
                              void* d_out, int out_size)
{
    const float* grid = (const float*)d_in[0];
    const int E = in_sizes[1] / 2;

    float* out    = (float*)d_out;
    float* nf     = out;                    // [NODES, C]
    float* ei_out = out + NF_ELEMS;         // [2, E] as float
    float* attr   = ei_out + 2 * (size_t)E; // [E, 2]

    fused_kernel<<<ATTR_BLOCKS + TRANS_BLOCKS + EW_BLOCKS, 256>>>(
        grid, nf, ei_out, attr, E);
}